// round 1
// baseline (speedup 1.0000x reference)
#include <cuda_runtime.h>

#define NU 100000
#define NI 50000
#define NN 150000
#define NP 150016     // padded to multiple of 128
#define DIM 64
#define EE 3200000
#define BP 16384

// Scratch (device globals are the sanctioned alloc-free workaround)
__device__ float g_dinv[NP];
__device__ float g_norm[EE];
__device__ float g_H[NP * DIM];    // current node features (residual stream)
__device__ float g_HW[NP * DIM];   // h @ W
__device__ float g_OUT[NP * DIM];  // conv accumulator

// ---------------- init: concat U,I into g_H ----------------
__global__ void k_concat(const float4* __restrict__ U, const float4* __restrict__ I) {
    int i = blockIdx.x * blockDim.x + threadIdx.x;
    const int nu4 = NU * DIM / 4;
    const int tot = NN * DIM / 4;
    if (i < tot) {
        float4 v = (i < nu4) ? U[i] : I[i - nu4];
        ((float4*)g_H)[i] = v;
    }
}

// ---------------- degree / norm precompute ----------------
__global__ void k_deg_init() {
    int i = blockIdx.x * blockDim.x + threadIdx.x;
    if (i < NP) g_dinv[i] = 1.0f;   // self-loop weight
}

__global__ void k_deg_accum(const int* __restrict__ dst, const float* __restrict__ ew) {
    int e = blockIdx.x * blockDim.x + threadIdx.x;
    if (e < EE) atomicAdd(&g_dinv[dst[e]], ew[e]);
}

__global__ void k_deg_fin() {
    int i = blockIdx.x * blockDim.x + threadIdx.x;
    if (i < NP) g_dinv[i] = rsqrtf(g_dinv[i]);   // deg >= 1 always
}

__global__ void k_norm(const int* __restrict__ src, const int* __restrict__ dst,
                       const float* __restrict__ ew) {
    int e = blockIdx.x * blockDim.x + threadIdx.x;
    if (e < EE) g_norm[e] = g_dinv[src[e]] * ew[e] * g_dinv[dst[e]];
}

// ---------------- GEMM: HW = H @ W ; OUT = dinv^2 * HW + b (self-loop fused) ---
// 64 threads / block, one row per thread, W staged in smem.
__global__ __launch_bounds__(64) void k_gemm(const float* __restrict__ W,
                                             const float* __restrict__ bias) {
    __shared__ float Ws[DIM * DIM];
    __shared__ float Xs[64 * 65];
    int row0 = blockIdx.x * 64;
    int tid = threadIdx.x;
    for (int i = tid; i < DIM * DIM; i += 64) Ws[i] = W[i];
    for (int idx = tid; idx < 64 * DIM; idx += 64) {
        int r = idx >> 6, c = idx & 63;
        Xs[r * 65 + c] = g_H[(row0 + r) * DIM + c];
    }
    __syncthreads();

    float4 acc[16];
#pragma unroll
    for (int j = 0; j < 16; j++) acc[j] = make_float4(0.f, 0.f, 0.f, 0.f);
    const float4* W4 = (const float4*)Ws;
#pragma unroll 4
    for (int k = 0; k < DIM; k++) {
        float xk = Xs[tid * 65 + k];
#pragma unroll
        for (int j = 0; j < 16; j++) {
            float4 w = W4[k * 16 + j];
            acc[j].x += xk * w.x; acc[j].y += xk * w.y;
            acc[j].z += xk * w.z; acc[j].w += xk * w.w;
        }
    }
    int r = row0 + tid;
    float di = g_dinv[r];
    float sn = di * di;   // self-loop norm
    const float4* b4 = (const float4*)bias;
#pragma unroll
    for (int j = 0; j < 16; j++) {
        ((float4*)g_HW)[r * 16 + j] = acc[j];
        float4 b = b4[j];
        float4 o = make_float4(fmaf(sn, acc[j].x, b.x), fmaf(sn, acc[j].y, b.y),
                               fmaf(sn, acc[j].z, b.z), fmaf(sn, acc[j].w, b.w));
        ((float4*)g_OUT)[r * 16 + j] = o;
    }
}

// ---------------- edge scatter: OUT[dst] += norm * HW[src] ----------------
// 16 threads per edge, each does one float4 vectorized reduction.
__global__ void k_scatter(const int* __restrict__ src, const int* __restrict__ dst) {
    int t = blockIdx.x * blockDim.x + threadIdx.x;
    int e = t >> 4;
    if (e >= EE) return;
    int g = t & 15;
    int s = __ldg(&src[e]);
    int d = __ldg(&dst[e]);
    float w = g_norm[e];
    float4 v = *(const float4*)&g_HW[s * DIM + g * 4];
    float* p = &g_OUT[d * DIM + g * 4];
    asm volatile("red.global.add.v4.f32 [%0], {%1, %2, %3, %4};"
                 :: "l"(p), "f"(w * v.x), "f"(w * v.y), "f"(w * v.z), "f"(w * v.w)
                 : "memory");
}

// ---------------- layernorm + relu + residual (in place on g_H) -------------
__global__ void k_ln(const float* __restrict__ gam, const float* __restrict__ bet) {
    int gtid = blockIdx.x * blockDim.x + threadIdx.x;
    int row = gtid >> 5;
    int lane = gtid & 31;
    if (row >= NN) return;
    float x0 = g_OUT[row * 64 + lane];
    float x1 = g_OUT[row * 64 + lane + 32];
    float s = x0 + x1;
#pragma unroll
    for (int o = 16; o > 0; o >>= 1) s += __shfl_xor_sync(0xffffffffu, s, o);
    float m = s * (1.0f / 64.0f);
    float d0 = x0 - m, d1 = x1 - m;
    float q = d0 * d0 + d1 * d1;
#pragma unroll
    for (int o = 16; o > 0; o >>= 1) q += __shfl_xor_sync(0xffffffffu, q, o);
    float rs = rsqrtf(q * (1.0f / 64.0f) + 1e-5f);
    float y0 = fmaxf(fmaf(d0 * rs, gam[lane], bet[lane]), 0.0f);
    float y1 = fmaxf(fmaf(d1 * rs, gam[lane + 32], bet[lane + 32]), 0.0f);
    g_H[row * 64 + lane]      += y0;
    g_H[row * 64 + lane + 32] += y1;
}

// ---------------- fused projection + dot + bias + clip ----------------
// Warp per pair; only the 2*B scored rows get projected (saves two full-N passes).
__global__ __launch_bounds__(256) void k_score(const int* __restrict__ users,
                                               const int* __restrict__ items,
                                               const float* __restrict__ Wp,
                                               const float* __restrict__ bp,
                                               const float* __restrict__ bu,
                                               const float* __restrict__ bi,
                                               const float* __restrict__ mu,
                                               float* __restrict__ out) {
    __shared__ float Wps[64 * 64];
    __shared__ float bps[64];
    int tid = threadIdx.x;
    for (int i = tid; i < 64 * 64; i += 256) Wps[i] = Wp[i];
    if (tid < 64) bps[tid] = bp[tid];
    __syncthreads();
    int wid = tid >> 5, lane = tid & 31;
    int pair = blockIdx.x * 8 + wid;
    if (pair >= BP) return;
    int u = users[pair], it = items[pair];
    const float* hu = &g_H[u * 64];
    const float* hi = &g_H[(NU + it) * 64];
    float a0 = hu[lane], a1 = hu[lane + 32];
    float c0 = hi[lane], c1 = hi[lane + 32];
    float pu0 = bps[lane], pu1 = bps[lane + 32];
    float pi0 = bps[lane], pi1 = bps[lane + 32];
#pragma unroll
    for (int k = 0; k < 32; k++) {
        float ak = __shfl_sync(0xffffffffu, a0, k);
        float ck = __shfl_sync(0xffffffffu, c0, k);
        float w0 = Wps[k * 64 + lane], w1 = Wps[k * 64 + lane + 32];
        pu0 += ak * w0; pu1 += ak * w1;
        pi0 += ck * w0; pi1 += ck * w1;
    }
#pragma unroll
    for (int k = 0; k < 32; k++) {
        float ak = __shfl_sync(0xffffffffu, a1, k);
        float ck = __shfl_sync(0xffffffffu, c1, k);
        float w0 = Wps[(k + 32) * 64 + lane], w1 = Wps[(k + 32) * 64 + lane + 32];
        pu0 += ak * w0; pu1 += ak * w1;
        pi0 += ck * w0; pi1 += ck * w1;
    }
    float dt = pu0 * pi0 + pu1 * pi1;
#pragma unroll
    for (int o = 16; o > 0; o >>= 1) dt += __shfl_xor_sync(0xffffffffu, dt, o);
    if (lane == 0) {
        float sv = dt + bu[u] + bi[it] + mu[0];
        out[pair] = fminf(fmaxf(sv, 1.0f), 5.0f);
    }
}

extern "C" void kernel_launch(void* const* d_in, const int* in_sizes, int n_in,
                              void* d_out, int out_size) {
    (void)in_sizes; (void)n_in; (void)out_size;
    const int*   users = (const int*)d_in[0];
    const int*   items = (const int*)d_in[1];
    const int*   ei    = (const int*)d_in[2];
    const float* ew    = (const float*)d_in[3];
    const float* U     = (const float*)d_in[4];
    const float* I     = (const float*)d_in[5];
    const float* W0    = (const float*)d_in[6];
    const float* b0    = (const float*)d_in[7];
    const float* g0    = (const float*)d_in[8];
    const float* be0   = (const float*)d_in[9];
    const float* W1    = (const float*)d_in[10];
    const float* b1    = (const float*)d_in[11];
    const float* g1    = (const float*)d_in[12];
    const float* be1   = (const float*)d_in[13];
    const float* Wp    = (const float*)d_in[14];
    const float* bp    = (const float*)d_in[15];
    const float* bu    = (const float*)d_in[16];
    const float* bi    = (const float*)d_in[17];
    const float* mu    = (const float*)d_in[18];
    float* out = (float*)d_out;
    const int* src = ei;
    const int* dst = ei + EE;

    k_concat<<<(NN * DIM / 4 + 255) / 256, 256>>>((const float4*)U, (const float4*)I);
    k_deg_init<<<(NP + 255) / 256, 256>>>();
    k_deg_accum<<<(EE + 255) / 256, 256>>>(dst, ew);
    k_deg_fin<<<(NP + 255) / 256, 256>>>();
    k_norm<<<(EE + 255) / 256, 256>>>(src, dst, ew);

    // layer 0
    k_gemm<<<NP / 64, 64>>>(W0, b0);
    k_scatter<<<(EE * 16 + 255) / 256, 256>>>(src, dst);
    k_ln<<<(NN * 32 + 255) / 256, 256>>>(g0, be0);

    // layer 1
    k_gemm<<<NP / 64, 64>>>(W1, b1);
    k_scatter<<<(EE * 16 + 255) / 256, 256>>>(src, dst);
    k_ln<<<(NN * 32 + 255) / 256, 256>>>(g1, be1);

    // fused projection + scoring
    k_score<<<BP / 8, 256>>>(users, items, Wp, bp, bu, bi, mu, out);
}

// round 2
// speedup vs baseline: 1.4782x; 1.4782x over previous
#include <cuda_runtime.h>

#define NU 100000
#define NI 50000
#define NN 150000
#define NP 150016        // padded
#define NSB 147          // scan blocks of 1024 over NP
#define DIM 64
#define EE 3200000
#define BP 16384

// ---- device scratch (alloc-free) ----
__device__ float g_dinv[NP];
__device__ int   g_cnt[NP];
__device__ float g_deg[NP];
__device__ int   g_offs[NP + 1];
__device__ int   g_cur[NP];
__device__ int   g_bsum[NSB];
__device__ int2  g_csr[EE];        // (src, norm-as-bits)
__device__ float g_H[NP * DIM];    // residual stream
__device__ float g_HW[NP * DIM];   // h @ W

// ---------------- concat U,I ----------------
__global__ void k_concat(const float4* __restrict__ U, const float4* __restrict__ I) {
    int i = blockIdx.x * blockDim.x + threadIdx.x;
    const int nu4 = NU * DIM / 4;
    const int tot = NN * DIM / 4;
    if (i < tot) {
        float4 v = (i < nu4) ? U[i] : I[i - nu4];
        ((float4*)g_H)[i] = v;
    }
}

// ---------------- init counters ----------------
__global__ void k_init() {
    int i = blockIdx.x * blockDim.x + threadIdx.x;
    if (i < NP) { g_deg[i] = 1.0f; g_cnt[i] = 0; }   // deg starts at self-loop weight
}

// ---------------- histogram: counts + weighted degree ----------------
__global__ void k_hist(const int* __restrict__ dst, const float* __restrict__ ew) {
    int e = blockIdx.x * blockDim.x + threadIdx.x;
    if (e < EE) {
        int d = dst[e];
        atomicAdd(&g_cnt[d], 1);
        atomicAdd(&g_deg[d], ew[e]);
    }
}

__global__ void k_dinv() {
    int i = blockIdx.x * blockDim.x + threadIdx.x;
    if (i < NP) g_dinv[i] = rsqrtf(g_deg[i]);
}

// ---------------- prefix scan over g_cnt -> g_offs ----------------
__device__ __forceinline__ int warp_incl_scan(int x, int lane) {
#pragma unroll
    for (int o = 1; o < 32; o <<= 1) {
        int y = __shfl_up_sync(0xffffffffu, x, o);
        if (lane >= o) x += y;
    }
    return x;
}

__global__ __launch_bounds__(256) void k_scan1() {
    __shared__ int wsum[8];
    int t = threadIdx.x, lane = t & 31, wid = t >> 5;
    int base = blockIdx.x * 1024 + t * 4;
    int v[4], s = 0;
#pragma unroll
    for (int j = 0; j < 4; j++) {
        v[j] = (base + j < NP) ? g_cnt[base + j] : 0;
        s += v[j];
    }
    int incl = warp_incl_scan(s, lane);
    if (lane == 31) wsum[wid] = incl;
    __syncthreads();
    if (t == 0) {
        int run = 0;
#pragma unroll
        for (int i = 0; i < 8; i++) { int tmp = wsum[i]; wsum[i] = run; run += tmp; }
    }
    __syncthreads();
    int excl = incl - s + wsum[wid];
    int run = excl;
#pragma unroll
    for (int j = 0; j < 4; j++) {
        if (base + j < NP) g_offs[base + j] = run;
        run += v[j];
    }
    if (t == 255) g_bsum[blockIdx.x] = excl + s;
}

__global__ __launch_bounds__(256) void k_scan2() {
    __shared__ int wsum[8];
    int t = threadIdx.x, lane = t & 31, wid = t >> 5;
    int x = (t < NSB) ? g_bsum[t] : 0;
    int incl = warp_incl_scan(x, lane);
    if (lane == 31) wsum[wid] = incl;
    __syncthreads();
    if (t == 0) {
        int run = 0;
#pragma unroll
        for (int i = 0; i < 8; i++) { int tmp = wsum[i]; wsum[i] = run; run += tmp; }
    }
    __syncthreads();
    if (t < NSB) g_bsum[t] = incl - x + wsum[wid];
}

__global__ void k_scan3() {
    int i = blockIdx.x * blockDim.x + threadIdx.x;
    if (i < NP) {
        int o = g_offs[i] + g_bsum[i >> 10];
        g_offs[i] = o;
        g_cur[i] = o;
    }
    if (i == 0) g_offs[NP] = EE;
}

// ---------------- CSR build: packed (src, norm) ----------------
__global__ void k_build(const int* __restrict__ src, const int* __restrict__ dst,
                        const float* __restrict__ ew) {
    int e = blockIdx.x * blockDim.x + threadIdx.x;
    if (e < EE) {
        int s = src[e], d = dst[e];
        float w = g_dinv[s] * ew[e] * g_dinv[d];
        int pos = atomicAdd(&g_cur[d], 1);
        g_csr[pos] = make_int2(s, __float_as_int(w));
    }
}

// ---------------- GEMM: HW = H @ W ----------------
__global__ __launch_bounds__(64) void k_gemm(const float* __restrict__ W) {
    __shared__ float Ws[DIM * DIM];
    __shared__ float Xs[64 * 65];
    int row0 = blockIdx.x * 64;
    int tid = threadIdx.x;
    for (int i = tid; i < DIM * DIM; i += 64) Ws[i] = W[i];
    for (int idx = tid; idx < 64 * DIM; idx += 64) {
        int r = idx >> 6, c = idx & 63;
        Xs[r * 65 + c] = g_H[(row0 + r) * DIM + c];
    }
    __syncthreads();

    float4 acc[16];
#pragma unroll
    for (int j = 0; j < 16; j++) acc[j] = make_float4(0.f, 0.f, 0.f, 0.f);
    const float4* W4 = (const float4*)Ws;
#pragma unroll 4
    for (int k = 0; k < DIM; k++) {
        float xk = Xs[tid * 65 + k];
#pragma unroll
        for (int j = 0; j < 16; j++) {
            float4 w = W4[k * 16 + j];
            acc[j].x += xk * w.x; acc[j].y += xk * w.y;
            acc[j].z += xk * w.z; acc[j].w += xk * w.w;
        }
    }
    int r = row0 + tid;
#pragma unroll
    for (int j = 0; j < 16; j++) ((float4*)g_HW)[r * 16 + j] = acc[j];
}

// ---------------- fused conv gather + bias + LN + ReLU + residual ----------------
// One warp per destination node; float2 per lane covers the 64 features.
__global__ __launch_bounds__(256) void k_conv_ln(const float* __restrict__ bias,
                                                 const float* __restrict__ gam,
                                                 const float* __restrict__ bet) {
    int gw = (blockIdx.x * blockDim.x + threadIdx.x) >> 5;
    int lane = threadIdx.x & 31;
    if (gw >= NN) return;
    int d = gw;
    int e0 = g_offs[d], e1 = g_offs[d + 1];
    const float2* __restrict__ HW2 = (const float2*)g_HW;
    float ax = 0.f, ay = 0.f;
    int e = e0;
    for (; e + 1 < e1; e += 2) {
        int2 ca = __ldg(&g_csr[e]);
        int2 cb = __ldg(&g_csr[e + 1]);
        float wa = __int_as_float(ca.y), wb = __int_as_float(cb.y);
        float2 va = HW2[ca.x * 32 + lane];
        float2 vb = HW2[cb.x * 32 + lane];
        ax = fmaf(wa, va.x, ax); ay = fmaf(wa, va.y, ay);
        ax = fmaf(wb, vb.x, ax); ay = fmaf(wb, vb.y, ay);
    }
    if (e < e1) {
        int2 c = __ldg(&g_csr[e]);
        float w = __int_as_float(c.y);
        float2 v = HW2[c.x * 32 + lane];
        ax = fmaf(w, v.x, ax); ay = fmaf(w, v.y, ay);
    }
    // self-loop + bias
    float di = g_dinv[d];
    float sn = di * di;
    float2 hv = HW2[d * 32 + lane];
    float2 b2 = ((const float2*)bias)[lane];
    ax = fmaf(sn, hv.x, ax) + b2.x;
    ay = fmaf(sn, hv.y, ay) + b2.y;
    // layernorm over 64 (2 per lane)
    float s = ax + ay;
#pragma unroll
    for (int o = 16; o > 0; o >>= 1) s += __shfl_xor_sync(0xffffffffu, s, o);
    float m = s * (1.0f / 64.0f);
    float d0 = ax - m, d1 = ay - m;
    float q = d0 * d0 + d1 * d1;
#pragma unroll
    for (int o = 16; o > 0; o >>= 1) q += __shfl_xor_sync(0xffffffffu, q, o);
    float rs = rsqrtf(q * (1.0f / 64.0f) + 1e-5f);
    float2 g2 = ((const float2*)gam)[lane];
    float2 be2 = ((const float2*)bet)[lane];
    float y0 = fmaxf(fmaf(d0 * rs, g2.x, be2.x), 0.0f);
    float y1 = fmaxf(fmaf(d1 * rs, g2.y, be2.y), 0.0f);
    float2* H2 = (float2*)g_H;
    float2 res = H2[d * 32 + lane];
    H2[d * 32 + lane] = make_float2(res.x + y0, res.y + y1);
}

// ---------------- fused projection + dot + bias + clip ----------------
__global__ __launch_bounds__(256) void k_score(const int* __restrict__ users,
                                               const int* __restrict__ items,
                                               const float* __restrict__ Wp,
                                               const float* __restrict__ bp,
                                               const float* __restrict__ bu,
                                               const float* __restrict__ bi,
                                               const float* __restrict__ mu,
                                               float* __restrict__ out) {
    __shared__ float Wps[64 * 64];
    __shared__ float bps[64];
    int tid = threadIdx.x;
    for (int i = tid; i < 64 * 64; i += 256) Wps[i] = Wp[i];
    if (tid < 64) bps[tid] = bp[tid];
    __syncthreads();
    int wid = tid >> 5, lane = tid & 31;
    int pair = blockIdx.x * 8 + wid;
    if (pair >= BP) return;
    int u = users[pair], it = items[pair];
    const float* hu = &g_H[u * 64];
    const float* hi = &g_H[(NU + it) * 64];
    float a0 = hu[lane], a1 = hu[lane + 32];
    float c0 = hi[lane], c1 = hi[lane + 32];
    float pu0 = bps[lane], pu1 = bps[lane + 32];
    float pi0 = bps[lane], pi1 = bps[lane + 32];
#pragma unroll
    for (int k = 0; k < 32; k++) {
        float ak = __shfl_sync(0xffffffffu, a0, k);
        float ck = __shfl_sync(0xffffffffu, c0, k);
        float w0 = Wps[k * 64 + lane], w1 = Wps[k * 64 + lane + 32];
        pu0 += ak * w0; pu1 += ak * w1;
        pi0 += ck * w0; pi1 += ck * w1;
    }
#pragma unroll
    for (int k = 0; k < 32; k++) {
        float ak = __shfl_sync(0xffffffffu, a1, k);
        float ck = __shfl_sync(0xffffffffu, c1, k);
        float w0 = Wps[(k + 32) * 64 + lane], w1 = Wps[(k + 32) * 64 + lane + 32];
        pu0 += ak * w0; pu1 += ak * w1;
        pi0 += ck * w0; pi1 += ck * w1;
    }
    float dt = pu0 * pi0 + pu1 * pi1;
#pragma unroll
    for (int o = 16; o > 0; o >>= 1) dt += __shfl_xor_sync(0xffffffffu, dt, o);
    if (lane == 0) {
        float sv = dt + bu[u] + bi[it] + mu[0];
        out[pair] = fminf(fmaxf(sv, 1.0f), 5.0f);
    }
}

extern "C" void kernel_launch(void* const* d_in, const int* in_sizes, int n_in,
                              void* d_out, int out_size) {
    (void)in_sizes; (void)n_in; (void)out_size;
    const int*   users = (const int*)d_in[0];
    const int*   items = (const int*)d_in[1];
    const int*   ei    = (const int*)d_in[2];
    const float* ew    = (const float*)d_in[3];
    const float* U     = (const float*)d_in[4];
    const float* I     = (const float*)d_in[5];
    const float* W0    = (const float*)d_in[6];
    const float* b0    = (const float*)d_in[7];
    const float* g0    = (const float*)d_in[8];
    const float* be0   = (const float*)d_in[9];
    const float* W1    = (const float*)d_in[10];
    const float* b1    = (const float*)d_in[11];
    const float* g1    = (const float*)d_in[12];
    const float* be1   = (const float*)d_in[13];
    const float* Wp    = (const float*)d_in[14];
    const float* bp    = (const float*)d_in[15];
    const float* bu    = (const float*)d_in[16];
    const float* bi    = (const float*)d_in[17];
    const float* mu    = (const float*)d_in[18];
    float* out = (float*)d_out;
    const int* src = ei;
    const int* dst = ei + EE;

    k_concat<<<(NN * DIM / 4 + 255) / 256, 256>>>((const float4*)U, (const float4*)I);
    k_init<<<(NP + 255) / 256, 256>>>();
    k_hist<<<(EE + 255) / 256, 256>>>(dst, ew);
    k_dinv<<<(NP + 255) / 256, 256>>>();
    k_scan1<<<NSB, 256>>>();
    k_scan2<<<1, 256>>>();
    k_scan3<<<(NP + 255) / 256, 256>>>();
    k_build<<<(EE + 255) / 256, 256>>>(src, dst, ew);

    // layer 0
    k_gemm<<<NP / 64, 64>>>(W0);
    k_conv_ln<<<(NN + 7) / 8, 256>>>(b0, g0, be0);
    // layer 1
    k_gemm<<<NP / 64, 64>>>(W1);
    k_conv_ln<<<(NN + 7) / 8, 256>>>(b1, g1, be1);

    // fused projection + scoring
    k_score<<<BP / 8, 256>>>(users, items, Wp, bp, bu, bi, mu, out);
}

// round 3
// speedup vs baseline: 1.5709x; 1.0627x over previous
#include <cuda_runtime.h>

#define NU 100000
#define NI 50000
#define NN 150000
#define NP 150016        // padded
#define NSB 147          // scan blocks of 1024 over NP
#define DIM 64
#define EE 3200000
#define BP 16384

// ---- device scratch (alloc-free) ----
__device__ float g_dinv[NP];
__device__ int   g_cnt[NP];
__device__ float g_deg[NP];
__device__ int   g_offs[NP + 1];
__device__ int   g_cur[NP];
__device__ int   g_bsum[NSB];
__device__ int2  g_csr[EE];        // (src, norm-as-bits)
__device__ float g_H[NP * DIM];    // residual stream
__device__ float g_HW[NP * DIM];   // h @ W

// ---------------- concat U,I + init counters (fused) ----------------
__global__ void k_concat(const float4* __restrict__ U, const float4* __restrict__ I) {
    int i = blockIdx.x * blockDim.x + threadIdx.x;
    const int nu4 = NU * DIM / 4;
    const int tot = NN * DIM / 4;
    if (i < tot) {
        float4 v = (i < nu4) ? U[i] : I[i - nu4];
        ((float4*)g_H)[i] = v;
    }
    if (i < NP) { g_deg[i] = 1.0f; g_cnt[i] = 0; }
}

// ---------------- histogram: counts + weighted degree ----------------
__global__ void k_hist(const int* __restrict__ dst, const float* __restrict__ ew) {
    int e = blockIdx.x * blockDim.x + threadIdx.x;
    if (e < EE) {
        int d = dst[e];
        atomicAdd(&g_cnt[d], 1);
        atomicAdd(&g_deg[d], ew[e]);
    }
}

// ---------------- scan pass 1 (+ dinv fused) ----------------
__device__ __forceinline__ int warp_incl_scan(int x, int lane) {
#pragma unroll
    for (int o = 1; o < 32; o <<= 1) {
        int y = __shfl_up_sync(0xffffffffu, x, o);
        if (lane >= o) x += y;
    }
    return x;
}

__global__ __launch_bounds__(256) void k_scan1() {
    __shared__ int wsum[8];
    int t = threadIdx.x, lane = t & 31, wid = t >> 5;
    int base = blockIdx.x * 1024 + t * 4;
    int v[4], s = 0;
#pragma unroll
    for (int j = 0; j < 4; j++) {
        int idx = base + j;
        v[j] = (idx < NP) ? g_cnt[idx] : 0;
        s += v[j];
        if (idx < NP) g_dinv[idx] = rsqrtf(g_deg[idx]);   // fused
    }
    int incl = warp_incl_scan(s, lane);
    if (lane == 31) wsum[wid] = incl;
    __syncthreads();
    if (t == 0) {
        int run = 0;
#pragma unroll
        for (int i = 0; i < 8; i++) { int tmp = wsum[i]; wsum[i] = run; run += tmp; }
    }
    __syncthreads();
    int excl = incl - s + wsum[wid];
    int run = excl;
#pragma unroll
    for (int j = 0; j < 4; j++) {
        if (base + j < NP) g_offs[base + j] = run;
        run += v[j];
    }
    if (t == 255) g_bsum[blockIdx.x] = excl + s;
}

// ---------------- scan pass 2: each block reduces preceding bsums itself ----
__global__ __launch_bounds__(256) void k_scan3() {
    __shared__ int red[256];
    int t = threadIdx.x;
    int v = (t < NSB && t < blockIdx.x) ? g_bsum[t] : 0;
    red[t] = v;
    __syncthreads();
#pragma unroll
    for (int o = 128; o > 0; o >>= 1) {
        if (t < o) red[t] += red[t + o];
        __syncthreads();
    }
    int pref = red[0];
    int base = blockIdx.x * 1024;
#pragma unroll
    for (int j = 0; j < 4; j++) {
        int i = base + t + j * 256;
        if (i < NP) {
            int o = g_offs[i] + pref;
            g_offs[i] = o;
            g_cur[i] = o;
        }
    }
    if (blockIdx.x == 0 && t == 0) g_offs[NP] = EE;
}

// ---------------- CSR build: packed (src, norm) ----------------
__global__ void k_build(const int* __restrict__ src, const int* __restrict__ dst,
                        const float* __restrict__ ew) {
    int e = blockIdx.x * blockDim.x + threadIdx.x;
    if (e < EE) {
        int s = src[e], d = dst[e];
        float w = g_dinv[s] * ew[e] * g_dinv[d];
        int pos = atomicAdd(&g_cur[d], 1);
        g_csr[pos] = make_int2(s, __float_as_int(w));
    }
}

// ---------------- GEMM: HW = H @ W  (f32x2 packed FFMA) ----------------
__global__ __launch_bounds__(64) void k_gemm(const float* __restrict__ W) {
    __shared__ float2 Ws[DIM * 32];     // row-major, pairs of columns
    __shared__ float  Xs[64 * 65];
    int row0 = blockIdx.x * 64;
    int tid = threadIdx.x;
    for (int i = tid; i < DIM * 32; i += 64) Ws[i] = ((const float2*)W)[i];
    for (int idx = tid; idx < 64 * DIM; idx += 64) {
        int r = idx >> 6, c = idx & 63;
        Xs[r * 65 + c] = g_H[(row0 + r) * DIM + c];
    }
    __syncthreads();

    unsigned long long acc[32];
#pragma unroll
    for (int j = 0; j < 32; j++) acc[j] = 0ull;     // packed (0.f, 0.f)
    const unsigned long long* W2 = (const unsigned long long*)Ws;
#pragma unroll 4
    for (int k = 0; k < DIM; k++) {
        float xk = Xs[tid * 65 + k];
        unsigned long long x2;
        asm("mov.b64 %0, {%1, %1};" : "=l"(x2) : "f"(xk));
#pragma unroll
        for (int j = 0; j < 32; j++) {
            asm("fma.rn.f32x2 %0, %1, %2, %0;" : "+l"(acc[j]) : "l"(x2), "l"(W2[k * 32 + j]));
        }
    }
    int r = row0 + tid;
#pragma unroll
    for (int j = 0; j < 16; j++) {
        float4 o;
        asm("mov.b64 {%0, %1}, %2;" : "=f"(o.x), "=f"(o.y) : "l"(acc[2 * j]));
        asm("mov.b64 {%0, %1}, %2;" : "=f"(o.z), "=f"(o.w) : "l"(acc[2 * j + 1]));
        ((float4*)g_HW)[r * 16 + j] = o;
    }
}

// ---------------- fused conv gather + bias + LN + ReLU + residual ----------------
// One warp per destination node; float2 per lane covers the 64 features.
__global__ __launch_bounds__(256) void k_conv_ln(const float* __restrict__ bias,
                                                 const float* __restrict__ gam,
                                                 const float* __restrict__ bet) {
    int gw = (blockIdx.x * blockDim.x + threadIdx.x) >> 5;
    int lane = threadIdx.x & 31;
    if (gw >= NN) return;
    int d = gw;
    int e0 = g_offs[d], e1 = g_offs[d + 1];
    const float2* __restrict__ HW2 = (const float2*)g_HW;
    float ax = 0.f, ay = 0.f;
    int e = e0;
    for (; e + 3 < e1; e += 4) {
        int2 c0 = __ldg(&g_csr[e]);
        int2 c1 = __ldg(&g_csr[e + 1]);
        int2 c2 = __ldg(&g_csr[e + 2]);
        int2 c3 = __ldg(&g_csr[e + 3]);
        float2 v0 = HW2[c0.x * 32 + lane];
        float2 v1 = HW2[c1.x * 32 + lane];
        float2 v2 = HW2[c2.x * 32 + lane];
        float2 v3 = HW2[c3.x * 32 + lane];
        float w0 = __int_as_float(c0.y), w1 = __int_as_float(c1.y);
        float w2 = __int_as_float(c2.y), w3 = __int_as_float(c3.y);
        ax = fmaf(w0, v0.x, ax); ay = fmaf(w0, v0.y, ay);
        ax = fmaf(w1, v1.x, ax); ay = fmaf(w1, v1.y, ay);
        ax = fmaf(w2, v2.x, ax); ay = fmaf(w2, v2.y, ay);
        ax = fmaf(w3, v3.x, ax); ay = fmaf(w3, v3.y, ay);
    }
    for (; e < e1; e++) {
        int2 c = __ldg(&g_csr[e]);
        float w = __int_as_float(c.y);
        float2 v = HW2[c.x * 32 + lane];
        ax = fmaf(w, v.x, ax); ay = fmaf(w, v.y, ay);
    }
    // self-loop + bias
    float di = g_dinv[d];
    float sn = di * di;
    float2 hv = HW2[d * 32 + lane];
    float2 b2 = ((const float2*)bias)[lane];
    ax = fmaf(sn, hv.x, ax) + b2.x;
    ay = fmaf(sn, hv.y, ay) + b2.y;
    // layernorm over 64 (2 per lane)
    float s = ax + ay;
#pragma unroll
    for (int o = 16; o > 0; o >>= 1) s += __shfl_xor_sync(0xffffffffu, s, o);
    float m = s * (1.0f / 64.0f);
    float d0 = ax - m, d1 = ay - m;
    float q = d0 * d0 + d1 * d1;
#pragma unroll
    for (int o = 16; o > 0; o >>= 1) q += __shfl_xor_sync(0xffffffffu, q, o);
    float rs = rsqrtf(q * (1.0f / 64.0f) + 1e-5f);
    float2 g2 = ((const float2*)gam)[lane];
    float2 be2 = ((const float2*)bet)[lane];
    float y0 = fmaxf(fmaf(d0 * rs, g2.x, be2.x), 0.0f);
    float y1 = fmaxf(fmaf(d1 * rs, g2.y, be2.y), 0.0f);
    float2* H2 = (float2*)g_H;
    float2 res = H2[d * 32 + lane];
    H2[d * 32 + lane] = make_float2(res.x + y0, res.y + y1);
}

// ---------------- fused projection + dot + bias + clip ----------------
__global__ __launch_bounds__(256) void k_score(const int* __restrict__ users,
                                               const int* __restrict__ items,
                                               const float* __restrict__ Wp,
                                               const float* __restrict__ bp,
                                               const float* __restrict__ bu,
                                               const float* __restrict__ bi,
                                               const float* __restrict__ mu,
                                               float* __restrict__ out) {
    __shared__ float Wps[64 * 64];
    __shared__ float bps[64];
    int tid = threadIdx.x;
    for (int i = tid; i < 64 * 64; i += 256) Wps[i] = Wp[i];
    if (tid < 64) bps[tid] = bp[tid];
    __syncthreads();
    int wid = tid >> 5, lane = tid & 31;
    int pair = blockIdx.x * 8 + wid;
    if (pair >= BP) return;
    int u = users[pair], it = items[pair];
    const float* hu = &g_H[u * 64];
    const float* hi = &g_H[(NU + it) * 64];
    float a0 = hu[lane], a1 = hu[lane + 32];
    float c0 = hi[lane], c1 = hi[lane + 32];
    float pu0 = bps[lane], pu1 = bps[lane + 32];
    float pi0 = bps[lane], pi1 = bps[lane + 32];
#pragma unroll
    for (int k = 0; k < 32; k++) {
        float ak = __shfl_sync(0xffffffffu, a0, k);
        float ck = __shfl_sync(0xffffffffu, c0, k);
        float w0 = Wps[k * 64 + lane], w1 = Wps[k * 64 + lane + 32];
        pu0 += ak * w0; pu1 += ak * w1;
        pi0 += ck * w0; pi1 += ck * w1;
    }
#pragma unroll
    for (int k = 0; k < 32; k++) {
        float ak = __shfl_sync(0xffffffffu, a1, k);
        float ck = __shfl_sync(0xffffffffu, c1, k);
        float w0 = Wps[(k + 32) * 64 + lane], w1 = Wps[(k + 32) * 64 + lane + 32];
        pu0 += ak * w0; pu1 += ak * w1;
        pi0 += ck * w0; pi1 += ck * w1;
    }
    float dt = pu0 * pi0 + pu1 * pi1;
#pragma unroll
    for (int o = 16; o > 0; o >>= 1) dt += __shfl_xor_sync(0xffffffffu, dt, o);
    if (lane == 0) {
        float sv = dt + bu[u] + bi[it] + mu[0];
        out[pair] = fminf(fmaxf(sv, 1.0f), 5.0f);
    }
}

extern "C" void kernel_launch(void* const* d_in, const int* in_sizes, int n_in,
                              void* d_out, int out_size) {
    (void)in_sizes; (void)n_in; (void)out_size;
    const int*   users = (const int*)d_in[0];
    const int*   items = (const int*)d_in[1];
    const int*   ei    = (const int*)d_in[2];
    const float* ew    = (const float*)d_in[3];
    const float* U     = (const float*)d_in[4];
    const float* I     = (const float*)d_in[5];
    const float* W0    = (const float*)d_in[6];
    const float* b0    = (const float*)d_in[7];
    const float* g0    = (const float*)d_in[8];
    const float* be0   = (const float*)d_in[9];
    const float* W1    = (const float*)d_in[10];
    const float* b1    = (const float*)d_in[11];
    const float* g1    = (const float*)d_in[12];
    const float* be1   = (const float*)d_in[13];
    const float* Wp    = (const float*)d_in[14];
    const float* bp    = (const float*)d_in[15];
    const float* bu    = (const float*)d_in[16];
    const float* bi    = (const float*)d_in[17];
    const float* mu    = (const float*)d_in[18];
    float* out = (float*)d_out;
    const int* src = ei;
    const int* dst = ei + EE;

    k_concat<<<(NN * DIM / 4 + 255) / 256, 256>>>((const float4*)U, (const float4*)I);
    k_hist<<<(EE + 255) / 256, 256>>>(dst, ew);
    k_scan1<<<NSB, 256>>>();
    k_scan3<<<NSB, 256>>>();
    k_build<<<(EE + 255) / 256, 256>>>(src, dst, ew);

    // layer 0
    k_gemm<<<NP / 64, 64>>>(W0);
    k_conv_ln<<<(NN + 7) / 8, 256>>>(b0, g0, be0);
    // layer 1
    k_gemm<<<NP / 64, 64>>>(W1);
    k_conv_ln<<<(NN + 7) / 8, 256>>>(b1, g1, be1);

    // fused projection + scoring
    k_score<<<BP / 8, 256>>>(users, items, Wp, bp, bu, bi, mu, out);
}